// round 11
// baseline (speedup 1.0000x reference)
#include <cuda_runtime.h>

// PatchChamferDistance: B=32, G=64, P=256, D=3 (fp32)
// d2[i][j] = max(|p_i|^2 + |q_j|^2 - 2 p_i.q_j, 0)
// out = mean_patch( mean_i min_j d2 + mean_j min_i d2 )
//
// R11 = R10 (direction-split warps, pair-packed fma2 scan, integer min with
// +C bias) + 2 patches per CTA (grid 1024) so the whole launch fits in ONE
// wave (capacity ~10 CTAs/SM * 148 = 1480 > 1024), removing the ragged
// second wave of the 2048-CTA layout. Kernel is at the fma2 RF-bank wall
// (rt=3: 402M fma2 /32 *3 /592 SMSP = ~34 us); this recovers the geometry gap.

#define BGQ   2048
#define NP    256
#define NPAIR 128
#define T     128
#define PPC   2            // patches per CTA
#define BIAS  128.0f
#define POSINF_BITS 0x7F800000

typedef unsigned long long u64;

__device__ __forceinline__ u64 pk2(float a, float b) {
    u64 r;
    asm("mov.b64 %0, {%1, %2};" : "=l"(r) : "f"(a), "f"(b));
    return r;
}
__device__ __forceinline__ u64 fma2(u64 a, u64 b, u64 c) {
    u64 d;
    asm("fma.rn.f32x2 %0, %1, %2, %3;" : "=l"(d) : "l"(a), "l"(b), "l"(c));
    return d;
}
__device__ __forceinline__ void upk2i(u64 v, int& lo, int& hi) {
    asm("mov.b64 {%0, %1}, %2;" : "=r"(lo), "=r"(hi) : "l"(v));
}

__global__ void pcd_zero_kernel(float* out) { out[0] = 0.0f; }

__global__ __launch_bounds__(T)
void pcd_chamfer_kernel(const float* __restrict__ pred,
                        const float* __restrict__ tgt,
                        float* __restrict__ out)
{
    __shared__ ulonglong2 spA[NPAIR], spB[NPAIR];   // preds  (pair-packed)
    __shared__ ulonglong2 sqA[NPAIR], sqB[NPAIR];   // targets
    __shared__ float wsum[T / 32];

    const int t   = threadIdx.x;
    const int dir = t >> 6;          // 0 = forward (own pred), 1 = backward (own tgt)
    const int t2  = t & 63;

    const ulonglong2* ownA  = dir ? sqA : spA;
    const ulonglong2* ownB  = dir ? sqB : spB;
    const ulonglong2* scanA = dir ? spA : sqA;
    const ulonglong2* scanB = dir ? spB : sqB;

    float v = 0.f;                   // accumulated over PPC patches

#pragma unroll 1
    for (int pp = 0; pp < PPC; pp++) {
        const int patch = blockIdx.x * PPC + pp;
        const float* pb = pred + (size_t)patch * NP * 3;
        const float* qb = tgt  + (size_t)patch * NP * 3;

        // phase 1: thread t loads point pair (2t, 2t+1) of both clouds
        // A[jj] = {-2x0,-2x1, -2y0,-2y1}   B[jj] = {-2z0,-2z1, w0+C, w1+C}
        {
            int j0 = 2 * t;
            float x0 = pb[j0 * 3 + 0], y0 = pb[j0 * 3 + 1], z0 = pb[j0 * 3 + 2];
            float x1 = pb[j0 * 3 + 3], y1 = pb[j0 * 3 + 4], z1 = pb[j0 * 3 + 5];
            float w0 = x0 * x0 + y0 * y0 + z0 * z0;
            float w1 = x1 * x1 + y1 * y1 + z1 * z1;
            spA[t] = make_ulonglong2(pk2(-2.f * x0, -2.f * x1), pk2(-2.f * y0, -2.f * y1));
            spB[t] = make_ulonglong2(pk2(-2.f * z0, -2.f * z1), pk2(w0 + BIAS, w1 + BIAS));

            x0 = qb[j0 * 3 + 0]; y0 = qb[j0 * 3 + 1]; z0 = qb[j0 * 3 + 2];
            x1 = qb[j0 * 3 + 3]; y1 = qb[j0 * 3 + 4]; z1 = qb[j0 * 3 + 5];
            w0 = x0 * x0 + y0 * y0 + z0 * z0;
            w1 = x1 * x1 + y1 * y1 + z1 * z1;
            sqA[t] = make_ulonglong2(pk2(-2.f * x0, -2.f * x1), pk2(-2.f * y0, -2.f * y1));
            sqB[t] = make_ulonglong2(pk2(-2.f * z0, -2.f * z1), pk2(w0 + BIAS, w1 + BIAS));
        }
        __syncthreads();

        // phase 2: recover own 4 rows from smem (pairs t2, t2+64), pack {v,v}
        u64 x2[4], y2[4], z2[4];
        float wnc[4];                // own norm - BIAS (post-loop add)
#pragma unroll
        for (int h = 0; h < 2; h++) {
            ulonglong2 a = ownA[t2 + 64 * h];
            ulonglong2 b = ownB[t2 + 64 * h];
            int i0, i1;
            float m2x0, m2x1, m2y0, m2y1, m2z0, m2z1;
            upk2i(a.x, i0, i1); m2x0 = __int_as_float(i0); m2x1 = __int_as_float(i1);
            upk2i(a.y, i0, i1); m2y0 = __int_as_float(i0); m2y1 = __int_as_float(i1);
            upk2i(b.x, i0, i1); m2z0 = __int_as_float(i0); m2z1 = __int_as_float(i1);
            upk2i(b.y, i0, i1);
            float wb0 = __int_as_float(i0), wb1 = __int_as_float(i1);  // w + C
            float xx0 = -0.5f * m2x0, xx1 = -0.5f * m2x1;
            float yy0 = -0.5f * m2y0, yy1 = -0.5f * m2y1;
            float zz0 = -0.5f * m2z0, zz1 = -0.5f * m2z1;
            x2[2 * h]     = pk2(xx0, xx0);
            x2[2 * h + 1] = pk2(xx1, xx1);
            y2[2 * h]     = pk2(yy0, yy0);
            y2[2 * h + 1] = pk2(yy1, yy1);
            z2[2 * h]     = pk2(zz0, zz0);
            z2[2 * h + 1] = pk2(zz1, zz1);
            wnc[2 * h]     = wb0 - 2.f * BIAS;   // (w+C) - 2C = w - C
            wnc[2 * h + 1] = wb1 - 2.f * BIAS;
        }

        // int-min accumulators over (w_scan + C - 2 dot)  (all values > 0)
        int imn[4] = {POSINF_BITS, POSINF_BITS, POSINF_BITS, POSINF_BITS};

#pragma unroll 8
        for (int jj = 0; jj < NPAIR; jj++) {
            ulonglong2 a = scanA[jj];    // warp-uniform -> LDS broadcast
            ulonglong2 b = scanB[jj];
#pragma unroll
            for (int r = 0; r < 4; r++) {
                u64 acc = fma2(x2[r], a.x, b.y);
                acc = fma2(y2[r], a.y, acc);
                acc = fma2(z2[r], b.x, acc);
                int d0, d1;
                upk2i(acc, d0, d1);                  // raw float bits, all > 0
                imn[r] = min(imn[r], min(d0, d1));   // IMNMX (alu pipe)
            }
        }

        // add own norm (minus bias), clamp (commutes with min), accumulate
#pragma unroll
        for (int r = 0; r < 4; r++) {
            float m = __int_as_float(imn[r]);        // min (w_scan + C - 2dot)
            v += fmaxf(wnc[r] + m, 0.f);             // + w_own - C
        }

        __syncthreads();   // smem reuse: all reads done before next patch
    }

    // block reduction: 4 warps, one atomic per CTA (2 patches)
#pragma unroll
    for (int o = 16; o > 0; o >>= 1)
        v += __shfl_down_sync(0xffffffffu, v, o);
    if ((t & 31) == 0) wsum[t >> 5] = v;
    __syncthreads();
    if (t == 0) {
        float s = wsum[0] + wsum[1] + wsum[2] + wsum[3];
        atomicAdd(out, s * (1.0f / ((float)NP * (float)BGQ)));
    }
}

extern "C" void kernel_launch(void* const* d_in, const int* in_sizes, int n_in,
                              void* d_out, int out_size)
{
    const float* pred = (const float*)d_in[0];
    const float* tgt  = (const float*)d_in[1];
    float* out = (float*)d_out;

    pcd_zero_kernel<<<1, 1>>>(out);
    pcd_chamfer_kernel<<<BGQ / PPC, T>>>(pred, tgt, out);
}

// round 12
// speedup vs baseline: 1.0520x; 1.0520x over previous
#include <cuda_runtime.h>

// PatchChamferDistance: B=32, G=64, P=256, D=3 (fp32)
// d2[i][j] = max(|p_i|^2 + |q_j|^2 - 2 p_i.q_j, 0)
// out = mean_patch( mean_i min_j d2 + mean_j min_i d2 )
//
// R12 = R10 mainloop (best: direction-split warps, pair-packed fma2 scan,
// +C-bias integer min) with the zero-kernel ELIMINATED: single launch,
// last-CTA fence/counter writes out[0] and resets the device accumulator
// (replay-deterministic for CUDA-graph timing).
// Mainloop sits at the fma2 RF-bank wall (rt=3): ~36.8 us floor.

#define BGQ   2048
#define NP    256
#define NPAIR 128
#define T     128
#define BIAS  128.0f
#define POSINF_BITS 0x7F800000

typedef unsigned long long u64;

__device__ float    g_accum;    // zero-initialized at module load
__device__ unsigned g_count;    // reset by last CTA each run

__device__ __forceinline__ u64 pk2(float a, float b) {
    u64 r;
    asm("mov.b64 %0, {%1, %2};" : "=l"(r) : "f"(a), "f"(b));
    return r;
}
__device__ __forceinline__ u64 fma2(u64 a, u64 b, u64 c) {
    u64 d;
    asm("fma.rn.f32x2 %0, %1, %2, %3;" : "=l"(d) : "l"(a), "l"(b), "l"(c));
    return d;
}
__device__ __forceinline__ void upk2i(u64 v, int& lo, int& hi) {
    asm("mov.b64 {%0, %1}, %2;" : "=r"(lo), "=r"(hi) : "l"(v));
}

__global__ __launch_bounds__(T)
void pcd_chamfer_kernel(const float* __restrict__ pred,
                        const float* __restrict__ tgt,
                        float* __restrict__ out)
{
    __shared__ ulonglong2 spA[NPAIR], spB[NPAIR];   // preds  (pair-packed)
    __shared__ ulonglong2 sqA[NPAIR], sqB[NPAIR];   // targets
    __shared__ float wsum[T / 32];

    const int t     = threadIdx.x;
    const int patch = blockIdx.x;

    const float* pb = pred + (size_t)patch * NP * 3;
    const float* qb = tgt  + (size_t)patch * NP * 3;

    // phase 1: thread t loads point pair (2t, 2t+1) of both clouds
    // A[jj] = {-2x0,-2x1, -2y0,-2y1}   B[jj] = {-2z0,-2z1, w0+C, w1+C}
    {
        int j0 = 2 * t;
        float x0 = pb[j0 * 3 + 0], y0 = pb[j0 * 3 + 1], z0 = pb[j0 * 3 + 2];
        float x1 = pb[j0 * 3 + 3], y1 = pb[j0 * 3 + 4], z1 = pb[j0 * 3 + 5];
        float w0 = x0 * x0 + y0 * y0 + z0 * z0;
        float w1 = x1 * x1 + y1 * y1 + z1 * z1;
        spA[t] = make_ulonglong2(pk2(-2.f * x0, -2.f * x1), pk2(-2.f * y0, -2.f * y1));
        spB[t] = make_ulonglong2(pk2(-2.f * z0, -2.f * z1), pk2(w0 + BIAS, w1 + BIAS));

        x0 = qb[j0 * 3 + 0]; y0 = qb[j0 * 3 + 1]; z0 = qb[j0 * 3 + 2];
        x1 = qb[j0 * 3 + 3]; y1 = qb[j0 * 3 + 4]; z1 = qb[j0 * 3 + 5];
        w0 = x0 * x0 + y0 * y0 + z0 * z0;
        w1 = x1 * x1 + y1 * y1 + z1 * z1;
        sqA[t] = make_ulonglong2(pk2(-2.f * x0, -2.f * x1), pk2(-2.f * y0, -2.f * y1));
        sqB[t] = make_ulonglong2(pk2(-2.f * z0, -2.f * z1), pk2(w0 + BIAS, w1 + BIAS));
    }
    __syncthreads();

    const int dir = t >> 6;          // 0 = forward (own pred), 1 = backward (own tgt)
    const int t2  = t & 63;

    const ulonglong2* ownA  = dir ? sqA : spA;
    const ulonglong2* ownB  = dir ? sqB : spB;
    const ulonglong2* scanA = dir ? spA : sqA;
    const ulonglong2* scanB = dir ? spB : sqB;

    // phase 2: recover own 4 rows from smem (pairs t2 and t2+64), pack {v,v}
    u64 x2[4], y2[4], z2[4];
    float wnc[4];                    // own norm - BIAS (post-loop add)
#pragma unroll
    for (int h = 0; h < 2; h++) {
        ulonglong2 a = ownA[t2 + 64 * h];
        ulonglong2 b = ownB[t2 + 64 * h];
        int i0, i1;
        float m2x0, m2x1, m2y0, m2y1, m2z0, m2z1;
        upk2i(a.x, i0, i1); m2x0 = __int_as_float(i0); m2x1 = __int_as_float(i1);
        upk2i(a.y, i0, i1); m2y0 = __int_as_float(i0); m2y1 = __int_as_float(i1);
        upk2i(b.x, i0, i1); m2z0 = __int_as_float(i0); m2z1 = __int_as_float(i1);
        upk2i(b.y, i0, i1);
        float wb0 = __int_as_float(i0), wb1 = __int_as_float(i1);  // w + BIAS
        float xx0 = -0.5f * m2x0, xx1 = -0.5f * m2x1;
        float yy0 = -0.5f * m2y0, yy1 = -0.5f * m2y1;
        float zz0 = -0.5f * m2z0, zz1 = -0.5f * m2z1;
        x2[2 * h]     = pk2(xx0, xx0);
        x2[2 * h + 1] = pk2(xx1, xx1);
        y2[2 * h]     = pk2(yy0, yy0);
        y2[2 * h + 1] = pk2(yy1, yy1);
        z2[2 * h]     = pk2(zz0, zz0);
        z2[2 * h + 1] = pk2(zz1, zz1);
        wnc[2 * h]     = wb0 - 2.f * BIAS;   // (w+C) - 2C = w - C
        wnc[2 * h + 1] = wb1 - 2.f * BIAS;
    }

    // int-min accumulators over (w_scan + C - 2 dot)  (all values > 0)
    int imn[4] = {POSINF_BITS, POSINF_BITS, POSINF_BITS, POSINF_BITS};

#pragma unroll 8
    for (int jj = 0; jj < NPAIR; jj++) {
        ulonglong2 a = scanA[jj];    // warp-uniform -> LDS broadcast
        ulonglong2 b = scanB[jj];
#pragma unroll
        for (int r = 0; r < 4; r++) {
            u64 acc = fma2(x2[r], a.x, b.y);
            acc = fma2(y2[r], a.y, acc);
            acc = fma2(z2[r], b.x, acc);
            int d0, d1;
            upk2i(acc, d0, d1);                  // raw float bits, all > 0
            imn[r] = min(imn[r], min(d0, d1));   // IMNMX (alu pipe)
        }
    }

    // add own norm (minus bias), clamp (commutes with min), sum 4 rows
    float v = 0.f;
#pragma unroll
    for (int r = 0; r < 4; r++) {
        float m = __int_as_float(imn[r]);         // min (w_scan + C - 2dot)
        v += fmaxf(wnc[r] + m, 0.f);              // + w_own - C
    }

    // block reduction: 4 warps
#pragma unroll
    for (int o = 16; o > 0; o >>= 1)
        v += __shfl_down_sync(0xffffffffu, v, o);
    if ((t & 31) == 0) wsum[t >> 5] = v;
    __syncthreads();

    // last-CTA pattern: no separate zero kernel, single launch
    if (t == 0) {
        float s = wsum[0] + wsum[1] + wsum[2] + wsum[3];
        atomicAdd(&g_accum, s);
        __threadfence();
        unsigned done = atomicAdd(&g_count, 1u);
        if (done == (unsigned)(gridDim.x - 1)) {
            __threadfence();
            float total = *((volatile float*)&g_accum);
            out[0] = total * (1.0f / ((float)NP * (float)BGQ));
            // reset for next (graph-replayed) run — keeps launches deterministic
            g_accum = 0.f;
            __threadfence();
            g_count = 0u;
        }
    }
}

extern "C" void kernel_launch(void* const* d_in, const int* in_sizes, int n_in,
                              void* d_out, int out_size)
{
    const float* pred = (const float*)d_in[0];
    const float* tgt  = (const float*)d_in[1];
    float* out = (float*)d_out;

    pcd_chamfer_kernel<<<BGQ, T>>>(pred, tgt, out);
}